// round 9
// baseline (speedup 1.0000x reference)
#include <cuda_runtime.h>
#include <math.h>

#define Nn    10000
#define DEGc  16
#define Dn    17
#define E0    160000
#define ET    170000
#define FIN   512
#define H1    16
#define H2    32
#define NC    32
#define UMAX  153        // unique A-sums per column = 17*18/2 = 153
#define UHMAX 77
#define ST1   (H1 + 1)   // odd stride -> conflict-free lane reads
#define ST2   (H2 + 1)

typedef unsigned long long u64;

// ---------------- scratch (device globals; no allocation allowed) ----------
__device__ __align__(256) float g_g1[Nn * H1];
__device__ __align__(256) float g_g2[Nn * H2];
__device__ float g_c1[ET];
__device__ float g_c2[ET];
__device__ int   g_map[Dn * Dn];   // (e,j) -> unique-sum rank
__device__ int   g_Ssum[UMAX + 8]; // unique offset sums
__device__ int   g_bidx[Dn];       // k -> unique rank of offset O_k
__device__ int   g_U;              // count of unique sums

// ---------------- packed-f32x2 helpers -------------------------------------
__device__ __forceinline__ u64 fma2(u64 a, u64 b, u64 c) {
    u64 d; asm("fma.rn.f32x2 %0, %1, %2, %3;" : "=l"(d) : "l"(a), "l"(b), "l"(c)); return d;
}
__device__ __forceinline__ u64 add2(u64 a, u64 b) {
    u64 d; asm("add.rn.f32x2 %0, %1, %2;" : "=l"(d) : "l"(a), "l"(b)); return d;
}
__device__ __forceinline__ float ex2a(float x) {
    float r; asm("ex2.approx.ftz.f32 %0, %1;" : "=f"(r) : "f"(x)); return r;
}
__device__ __forceinline__ void lds2(const float* p, u64& a, u64& b) {
    unsigned s = (unsigned)__cvta_generic_to_shared(p);
    asm("ld.shared.v2.u64 {%0,%1}, [%2];" : "=l"(a), "=l"(b) : "r"(s));
}
__device__ __forceinline__ u64 pack2(float lo, float hi) {
    u64 v; asm("mov.b64 %0, {%1,%2};" : "=l"(v) : "f"(lo), "f"(hi)); return v;
}
__device__ __forceinline__ float hsum2(u64 v) {
    float lo, hi;
    asm("mov.b64 {%0,%1}, %2;" : "=f"(lo), "=f"(hi) : "l"(v));
    return lo + hi;
}

#define LOG2E10 14.4269504089f   //  10 * log2(e)
#define LOG2E20 28.8539008177f   //  20 * log2(e)

// ---------------- K0: build unique-sum tables (once per launch) ------------
__global__ void k_setup(const int* __restrict__ rows) {
    __shared__ int O[Dn];
    __shared__ int S[Dn * Dn];
    __shared__ int first[Dn * Dn];
    const int t = threadIdx.x;            // 320 threads
    if (t < Dn) O[t] = (t < DEGc) ? rows[t] : 0;
    __syncthreads();
    if (t < Dn * Dn) {
        int e = t / Dn, j = t - (t / Dn) * Dn;
        int s = O[e] + O[j]; if (s >= Nn) s -= Nn;
        S[t] = s;
    }
    __syncthreads();
    if (t < Dn * Dn) {
        int f = 0;
        while (S[f] != S[t]) f++;
        first[t] = f;
    }
    __syncthreads();
    if (t < Dn * Dn) {
        int r = 0;
        for (int i = 0; i < first[t]; i++) r += (first[i] == i);
        g_map[t] = r;
        if (first[t] == t) g_Ssum[r] = S[t];
        if ((t % Dn) == Dn - 1) g_bidx[t / Dn] = r;   // (e=k, j=self) -> rank of O_k
    }
    __syncthreads();
    if (t == 0) {
        int u = 0;
        for (int i = 0; i < Dn * Dn; i++) u += (first[i] == i);
        g_U = u;
    }
}

// ---------------- K1: g1 = x @ W1 + b1, fma2 j-pairs -----------------------
// 8 rows/block, 64 threads: thread (il, jp) computes outputs (il, 2jp..2jp+1).
__global__ void __launch_bounds__(64) k_gemm1(const float* __restrict__ x,
                                              const float* __restrict__ W1,
                                              const float* __restrict__ b1) {
    __shared__ u64   sWp[FIN * 8];    // 32 KB (W1 packed in j-pairs)
    __shared__ float sX[8][FIN];      // 16 KB
    const int t = threadIdx.x;
    const u64* W1p = (const u64*)W1;
    for (int i = t; i < FIN * 8; i += 64) sWp[i] = W1p[i];
    const int rowBase = blockIdx.x * 8;
    for (int i = t; i < 8 * FIN; i += 64) {
        int r = i >> 9, c = i & (FIN - 1);
        sX[r][c] = x[(rowBase + r) * FIN + c];
    }
    __syncthreads();
    const int il = t >> 3, jp = t & 7;
    u64 acc0 = ((const u64*)b1)[jp], acc1 = 0, acc2 = 0, acc3 = 0;
    #pragma unroll 4
    for (int k = 0; k < FIN; k += 4) {
        acc0 = fma2(pack2(sX[il][k],     sX[il][k]),     sWp[(k)     * 8 + jp], acc0);
        acc1 = fma2(pack2(sX[il][k + 1], sX[il][k + 1]), sWp[(k + 1) * 8 + jp], acc1);
        acc2 = fma2(pack2(sX[il][k + 2], sX[il][k + 2]), sWp[(k + 2) * 8 + jp], acc2);
        acc3 = fma2(pack2(sX[il][k + 3], sX[il][k + 3]), sWp[(k + 3) * 8 + jp], acc3);
    }
    u64 acc = add2(add2(acc0, acc1), add2(acc2, acc3));
    ((u64*)g_g1)[(rowBase + il) * 8 + jp] = acc;
}

// ---------------- K2: layer-1 cross (H=16, 2 rows/lane) --------------------
__global__ void __launch_bounds__(96) k_cross1(const int* __restrict__ rows,
                                               const float* __restrict__ W2,
                                               const float* __restrict__ b2) {
    __shared__ __align__(16) float sB[Dn][H1];
    __shared__ float sA[UMAX * ST1];
    __shared__ float ssqa[UMAX];
    __shared__ int   sbid[Dn];
    __shared__ float R[UMAX];
    __shared__ float sW2[H1 * NC];
    const int c = blockIdx.x, t = threadIdx.x;
    const int U = g_U, UH = (U + 1) >> 1;
    if (t < Dn) sbid[t] = g_bidx[t];
    for (int i = t; i < H1 * NC; i += 96) sW2[i] = W2[i];
    for (int idx = t; idx < Dn * H1; idx += 96) {
        int k = idx / H1, h = idx - k * H1;
        int nk = (k < DEGc) ? rows[c * DEGc + k] : c;
        sB[k][h] = g_g1[nk * H1 + h];
    }
    for (int idx = t; idx < U * H1; idx += 96) {
        int row = idx / H1, h = idx - row * H1;
        int an = c + g_Ssum[row]; if (an >= Nn) an -= Nn;
        sA[row * ST1 + h] = g_g1[an * H1 + h];
    }
    __syncthreads();

    // phase A: load A rows + norms (barrier hoisted out of divergence)
    u64 a0[H1 / 2], a1[H1 / 2];
    float sqa0 = 0.f, sqa1 = 0.f;
    bool active = (t < UH), has1 = false;
    if (active) {
        const int t1 = t + UH;
        has1 = (t1 < U);
        const float* r0 = sA + t * ST1;
        const float* r1 = sA + (has1 ? t1 : t) * ST1;
        #pragma unroll
        for (int q = 0; q < H1 / 2; q++) {
            a0[q] = pack2(r0[2 * q], r0[2 * q + 1]);
            a1[q] = pack2(r1[2 * q], r1[2 * q + 1]);
        }
        u64 n0 = 0, n1 = 0, m0 = 0, m1 = 0;
        #pragma unroll
        for (int q = 0; q < H1 / 2; q += 2) {
            n0 = fma2(a0[q], a0[q], n0); n1 = fma2(a0[q + 1], a0[q + 1], n1);
            m0 = fma2(a1[q], a1[q], m0); m1 = fma2(a1[q + 1], a1[q + 1], m1);
        }
        sqa0 = LOG2E10 * hsum2(add2(n0, n1));
        sqa1 = LOG2E10 * hsum2(add2(m0, m1));
        ssqa[t] = sqa0;
        if (has1) ssqa[t + UH] = sqa1;
    }
    __syncthreads();

    if (active) {
        float s0 = 0.f, s1 = 0.f;
        #pragma unroll
        for (int k = 0; k < Dn; k++) {
            const float* bp = sB[k];
            const float sqb = ssqa[sbid[k]];
            u64 b[H1 / 2];
            #pragma unroll
            for (int q = 0; q < H1 / 2; q += 2) lds2(bp + 2 * q, b[q], b[q + 1]);
            u64 p00 = 0, p01 = 0, p10 = 0, p11 = 0;
            #pragma unroll
            for (int q = 0; q < H1 / 2; q += 2) {
                p00 = fma2(a0[q],     b[q],     p00);
                p01 = fma2(a0[q + 1], b[q + 1], p01);
                p10 = fma2(a1[q],     b[q],     p10);
                p11 = fma2(a1[q + 1], b[q + 1], p11);
            }
            s0 += ex2a(fmaf(hsum2(add2(p00, p01)), LOG2E20, -(sqa0 + sqb)));
            s1 += ex2a(fmaf(hsum2(add2(p10, p11)), LOG2E20, -(sqa1 + sqb)));
        }
        R[t] = s0;
        if (has1) R[t + UH] = s1;
    }
    __syncthreads();

    if (t < Dn) {                              // per-edge cross means
        const int* mp = g_map + t * Dn;
        float s = 0.f;
        #pragma unroll
        for (int j = 0; j < Dn; j++) s += R[mp[j]];
        g_c1[(t < DEGc) ? (c * DEGc + t) : (E0 + c)] = s * (1.0f / (Dn * Dn));
    }
    if (t >= 32 && t < 64) {                   // fused GCN agg + relu + @W2+b2
        const int l = t - 32;
        float rv = 0.f;
        if (l < H1) {
            float acc = 0.f;
            #pragma unroll
            for (int k = 0; k < Dn; k++) acc += sB[k][l];
            rv = fmaxf(acc * (1.0f / 17.0f), 0.f);
        }
        float acc = b2[l];
        #pragma unroll
        for (int h = 0; h < H1; h++) {
            float rh = __shfl_sync(0xffffffffu, rv, h);
            acc += rh * sW2[h * NC + l];
        }
        g_g2[c * NC + l] = acc;
    }
}

// ---------------- K3: layer-2 cross (H=32, H-split, 2 rows/lane) -----------
__global__ void __launch_bounds__(192) k_cross2(const int* __restrict__ rows,
                                                float* __restrict__ out) {
    __shared__ __align__(16) float sB[Dn][H2];
    __shared__ float sA[UMAX * ST2];                 // 153*33*4 = 20.2 KB
    __shared__ float ssqa[UMAX];
    __shared__ int   sbid[Dn];
    __shared__ float spart[2][2][Dn][UHMAX];         // [hgroup][rowslot][k][wt] ~20.9 KB
    __shared__ float R[UMAX];
    const int c = blockIdx.x, t = threadIdx.x;
    const int U = g_U, UH = (U + 1) >> 1;
    if (t < Dn) sbid[t] = g_bidx[t];
    for (int idx = t; idx < Dn * H2; idx += 192) {
        int k = idx / H2, h = idx - k * H2;
        int nk = (k < DEGc) ? rows[c * DEGc + k] : c;
        sB[k][h] = g_g2[nk * H2 + h];
    }
    for (int idx = t; idx < U * H2; idx += 192) {
        int row = idx / H2, h = idx - row * H2;
        int an = c + g_Ssum[row]; if (an >= Nn) an -= Nn;
        sA[row * ST2 + h] = g_g2[an * H2 + h];
    }
    __syncthreads();

    // full-H norms (conflict-free: stride 33)
    if (t < U) {
        const float* ar = sA + t * ST2;
        float n = 0.f;
        #pragma unroll
        for (int h = 0; h < H2; h++) n = fmaf(ar[h], ar[h], n);
        ssqa[t] = LOG2E10 * n;
    }

    // phase B: half-H partial dots; group gid handles h in [gid*16, gid*16+16)
    const int gid = (t >= 96) ? 1 : 0;
    const int wt  = t - 96 * gid;
    if (wt < UH) {
        const int  t1 = wt + UH;
        const bool has1 = (t1 < U);
        const float* r0 = sA + wt * ST2 + gid * 16;
        const float* r1 = sA + (has1 ? t1 : wt) * ST2 + gid * 16;
        u64 a0[8], a1[8];
        #pragma unroll
        for (int q = 0; q < 8; q++) {
            a0[q] = pack2(r0[2 * q], r0[2 * q + 1]);
            a1[q] = pack2(r1[2 * q], r1[2 * q + 1]);
        }
        #pragma unroll
        for (int k = 0; k < Dn; k++) {
            const float* bp = &sB[k][gid * 16];
            u64 b[8];
            #pragma unroll
            for (int q = 0; q < 8; q += 2) lds2(bp + 2 * q, b[q], b[q + 1]);
            u64 p00 = 0, p01 = 0, p10 = 0, p11 = 0;
            #pragma unroll
            for (int q = 0; q < 8; q += 2) {
                p00 = fma2(a0[q],     b[q],     p00);
                p01 = fma2(a0[q + 1], b[q + 1], p01);
                p10 = fma2(a1[q],     b[q],     p10);
                p11 = fma2(a1[q + 1], b[q + 1], p11);
            }
            spart[gid][0][k][wt] = hsum2(add2(p00, p01));
            spart[gid][1][k][wt] = hsum2(add2(p10, p11));
        }
    }
    __syncthreads();

    // phase C: combine halves + exp
    if (t < U) {
        const int slot = (t >= UH) ? 1 : 0;
        const int w2   = t - slot * UH;
        const float sqa = ssqa[t];
        float s = 0.f;
        #pragma unroll
        for (int k = 0; k < Dn; k++) {
            float dot = spart[0][slot][k][w2] + spart[1][slot][k][w2];
            float sqb = ssqa[sbid[k]];
            s += ex2a(fmaf(dot, LOG2E20, -(sqa + sqb)));
        }
        R[t] = s;
    }
    __syncthreads();

    if (t < Dn) {
        const int* mp = g_map + t * Dn;
        float s = 0.f;
        #pragma unroll
        for (int j = 0; j < Dn; j++) s += R[mp[j]];
        g_c2[(t < DEGc) ? (c * DEGc + t) : (E0 + c)] = s * (1.0f / (Dn * Dn));
    }
    if (t >= 32 && t < 64) {                   // fused GCN agg + log_softmax
        const int l = t - 32;
        float acc = 0.f;
        #pragma unroll
        for (int k = 0; k < Dn; k++) acc += sB[k][l];
        acc *= (1.0f / 17.0f);
        float m = acc;
        #pragma unroll
        for (int d = 16; d >= 1; d >>= 1) m = fmaxf(m, __shfl_xor_sync(0xffffffffu, m, d));
        float ex = __expf(acc - m);
        float s = ex;
        #pragma unroll
        for (int d = 16; d >= 1; d >>= 1) s += __shfl_xor_sync(0xffffffffu, s, d);
        out[c * NC + l] = acc - m - logf(s);
    }
}

// ---------------- K4: assemble both MMD outputs ----------------------------
__global__ void k_mmd(const int* __restrict__ rows, const int* __restrict__ cols,
                      float* __restrict__ m1, float* __restrict__ m2) {
    int e = blockIdx.x * blockDim.x + threadIdx.x;
    if (e >= ET) return;
    int r, cc;
    if (e < E0) { r = rows[e]; cc = cols[e]; } else { r = cc = e - E0; }
    m1[e] = g_c1[E0 + r] + g_c1[E0 + cc] - 2.0f * g_c1[e];
    m2[e] = g_c2[E0 + r] + g_c2[E0 + cc] - 2.0f * g_c2[e];
}

// ---------------- launch ---------------------------------------------------
extern "C" void kernel_launch(void* const* d_in, const int* in_sizes, int n_in,
                              void* d_out, int out_size) {
    const float* x  = (const float*)d_in[0];
    const int*   ei = (const int*)d_in[1];
    const float* W1 = (const float*)d_in[2];
    const float* b1 = (const float*)d_in[3];
    const float* W2 = (const float*)d_in[4];
    const float* b2 = (const float*)d_in[5];
    float* out = (float*)d_out;

    const int* rows = ei;
    const int* cols = ei + E0;

    k_setup<<<1, 320>>>(rows);
    k_gemm1<<<Nn / 8, 64>>>(x, W1, b1);
    k_cross1<<<Nn, 96>>>(rows, W2, b2);
    k_cross2<<<Nn, 192>>>(rows, out);
    k_mmd<<<(ET + 255) / 256, 256>>>(rows, cols, out + Nn * NC, out + Nn * NC + ET);
}